// round 10
// baseline (speedup 1.0000x reference)
#include <cuda_runtime.h>
#include <cuda_bf16.h>

#define N_PTS   4096
#define NSAMPLE 9
#define TOPK    5
#define R2      0.01f
#define H2      0.0144f
#define EPS_    1e-12f
#define MAXB    8
#define GRID_D  10
#define NCELL   1000
#define IMAX    0x7fffffff

#define LPQ     4                          // lanes per query
#define QPB     32                         // queries per block
#define TPB_G   (QPB * LPQ)                // 128 threads
#define GBLK_PER_BATCH (N_PTS / QPB)       // 128 blocks per batch
#define CAP     64                         // in-ball buffer slots per query

// cell-sorted points: xyz + original index in .w
__device__ float4 g_pts[MAXB * N_PTS];
// points by ORIGINAL index: xyz + cell id in .w (epilogue reads xyz only)
__device__ float4 g_org[MAXB * N_PTS];
__device__ int    g_hist[MAXB * NCELL];    // zero at load; re-zeroed by density_scan
__device__ int    g_cur [MAXB * NCELL];
__device__ int    g_cs  [MAXB * (NCELL + 1)];
__device__ float  g_partials[MAXB * GBLK_PER_BATCH];
__device__ unsigned int g_ticket;          // zero-init; reset by last block each launch

// ---------------- Kernel A1: cell ids + histogram (wide) -------------------
__global__ void __launch_bounds__(256)
density_cells(const float* __restrict__ pred) {
    const int b   = blockIdx.x >> 4;              // 16 blocks per batch
    const int sub = blockIdx.x & 15;
    const int i   = sub * 256 + threadIdx.x;      // 0..4095
    const float* pb = pred + (size_t)b * N_PTS * 3;

    float x = pb[i * 3 + 0], y = pb[i * 3 + 1], z = pb[i * 3 + 2];
    int cx = min((int)(x * 10.0f), GRID_D - 1);
    int cy = min((int)(y * 10.0f), GRID_D - 1);
    int cz = min((int)(z * 10.0f), GRID_D - 1);
    int c = cz * 100 + cy * 10 + cx;
    g_org[b * N_PTS + i] = make_float4(x, y, z, __int_as_float(c));
    atomicAdd(&g_hist[b * NCELL + c], 1);
}

// ---------------- Kernel A2: per-batch scan of the histogram ---------------
__global__ void __launch_bounds__(1024)
density_scan() {
    __shared__ int wsum[32];
    const int b    = blockIdx.x;
    const int tid  = threadIdx.x;
    const int lane = tid & 31;
    const int wid  = tid >> 5;

    const int h = (tid < NCELL) ? g_hist[b * NCELL + tid] : 0;
    if (tid < NCELL) g_hist[b * NCELL + tid] = 0;   // re-zero for next launch/replay
    int x = h;
#pragma unroll
    for (int off = 1; off < 32; off <<= 1) {
        int y = __shfl_up_sync(0xffffffffu, x, off);
        if (lane >= off) x += y;
    }
    if (lane == 31) wsum[wid] = x;
    __syncthreads();
    if (wid == 0) {
        int ws = wsum[lane];
        int wx = ws;
#pragma unroll
        for (int off = 1; off < 32; off <<= 1) {
            int y = __shfl_up_sync(0xffffffffu, wx, off);
            if (lane >= off) wx += y;
        }
        wsum[lane] = wx - ws;
    }
    __syncthreads();
    const int incl = x + wsum[wid];              // inclusive over cells [0..tid]

    if (tid == 0) g_cs[b * (NCELL + 1)] = 0;
    if (tid < NCELL) {
        g_cs [b * (NCELL + 1) + tid + 1] = incl;
        g_cur[b * NCELL + tid]           = incl - h;   // exclusive prefix = cstart
    }
}

// ---------------- Kernel A3: scatter into sorted order (wide) --------------
__global__ void __launch_bounds__(256)
density_scatter() {
    const int b   = blockIdx.x >> 4;
    const int sub = blockIdx.x & 15;
    const int i   = sub * 256 + threadIdx.x;

    float4 f = g_org[b * N_PTS + i];
    int c = __float_as_int(f.w);
    int pos = atomicAdd(&g_cur[b * NCELL + c], 1);
    g_pts[b * N_PTS + pos] = make_float4(f.x, f.y, f.z, __int_as_float(i));
}

// ---------------- Kernel B: quad-cooperative, deferred selection -----------
__global__ void __launch_bounds__(TPB_G)
density_group(float* __restrict__ out, float inv_count) {
    __shared__ int   sbuf[QPB * CAP];      // in-ball original indices per query
    __shared__ int   scnt[QPB];
    __shared__ float red[TPB_G / 32];
    __shared__ int   is_last;

    const int b     = blockIdx.x / GBLK_PER_BATCH;
    const int blk   = blockIdx.x % GBLK_PER_BATCH;
    const int goff  = b * N_PTS;
    const int csoff = b * (NCELL + 1);

    const int tid    = threadIdx.x;
    const int lane   = tid & 31;
    const int tq     = tid & (LPQ - 1);      // lane within quad
    const int qlocal = tid >> 2;             // query within block
    const int t      = blk * QPB + qlocal;   // query in sorted order

    if (tq == 0) scnt[qlocal] = 0;
    __syncwarp();

    const float4 q = __ldg(&g_pts[goff + t]);

    const int cy = min((int)(q.y * 10.0f), GRID_D - 1);
    const int cz = min((int)(q.z * 10.0f), GRID_D - 1);
    const int y0 = max(cy - 1, 0), y1 = min(cy + 1, GRID_D - 1);
    const int z0 = max(cz - 1, 0), z1 = min(cz + 1, GRID_D - 1);

    // scan phase: O(1) append of in-ball original indices (no ordering needed)
    for (int zz = z0; zz <= z1; zz++) {
        const float dzb = fmaxf(0.0f, fmaxf(zz * 0.1f - q.z, q.z - (zz + 1) * 0.1f));
        const float dz2 = dzb * dzb;
        for (int yy = y0; yy <= y1; yy++) {
            const float dyb = fmaxf(0.0f, fmaxf(yy * 0.1f - q.y, q.y - (yy + 1) * 0.1f));
            const float rem = R2 + 1e-7f - fmaf(dyb, dyb, dz2);
            if (rem < 0.0f) continue;                 // row can't contain in-ball pts
            const float dxm = sqrtf(rem);             // max |px - qx| for this row
            const int xa = max(0, (int)((q.x - dxm) * 10.0f));
            const int xb = min(GRID_D - 1, (int)((q.x + dxm) * 10.0f));

            const int rowbase = zz * 100 + yy * 10;
            const int jb = __ldg(&g_cs[csoff + rowbase + xa]);
            const int je = __ldg(&g_cs[csoff + rowbase + xb + 1]);

            // software-pipelined candidate loop (prefetch next float4)
            int j = jb + tq;
            bool have = j < je;
            float4 pn;
            if (have) pn = __ldg(&g_pts[goff + j]);
            while (have) {
                const float4 p = pn;
                const int jn = j + LPQ;
                have = jn < je;
                if (have) pn = __ldg(&g_pts[goff + jn]);
                j = jn;

                float dx  = q.x - p.x;
                float dy  = q.y - p.y;
                float dzp = q.z - p.z;
                float d2 = fmaf(dx, dx, fmaf(dy, dy, dzp * dzp));
                if (d2 <= R2) {
                    int pos = atomicAdd(&scnt[qlocal], 1);
                    if (pos < CAP) sbuf[qlocal * CAP + pos] = __float_as_int(p.w);
                }
            }
        }
    }
    __syncwarp();   // quad's appends visible to quad's lanes

    // selection phase: 9 smallest indices from the ~17 buffered entries
    const int nh = min(scnt[qlocal], CAP);
    int idx9[NSAMPLE];
#pragma unroll
    for (int k = 0; k < NSAMPLE; k++) idx9[k] = IMAX;

    for (int e = tq; e < nh; e += LPQ) {
        int ci = sbuf[qlocal * CAP + e];
        if (ci < idx9[NSAMPLE - 1]) {
#pragma unroll
            for (int k = 0; k < NSAMPLE; k++) {   // branchless IMNMX chain
                int lo = min(idx9[k], ci);
                ci      = max(idx9[k], ci);
                idx9[k] = lo;
            }
        }
    }

    // quad merge (indices only): 9 pop-min rounds over 4 sorted per-lane lists
    int mi9[NSAMPLE];
#pragma unroll
    for (int k = 0; k < NSAMPLE; k++) {
        int bi = idx9[0];
        int oi = __shfl_xor_sync(0xffffffffu, bi, 1);
        bi = min(bi, oi);
        oi = __shfl_xor_sync(0xffffffffu, bi, 2);
        bi = min(bi, oi);
        mi9[k] = bi;
        if (idx9[0] == bi && bi != IMAX) {   // this lane pops its head
#pragma unroll
            for (int s = 0; s < NSAMPLE - 1; s++) idx9[s] = idx9[s + 1];
            idx9[NSAMPLE - 1] = IMAX;
        }
    }

    // epilogue on quad leader: recompute the 9 values (bit-identical fmaf form)
    float acc = 0.0f;
    if (tq == 0) {
        float m9[NSAMPLE];
#pragma unroll
        for (int k = 0; k < NSAMPLE; k++) {
            const int ik = (mi9[k] == IMAX) ? mi9[0] : mi9[k];
            const float4 p = __ldg(&g_org[goff + ik]);
            float dx = q.x - p.x, dy = q.y - p.y, dzp = q.z - p.z;
            m9[k] = fmaf(dx, dx, fmaf(dy, dy, dzp * dzp));
        }

#pragma unroll
        for (int i = 0; i < TOPK; i++) {
            int   mi = i;
            float mv = m9[i];
#pragma unroll
            for (int j = i + 1; j < NSAMPLE; j++)
                if (m9[j] < mv) { mv = m9[j]; mi = j; }
            m9[mi] = m9[i];
            m9[i]  = mv;
            if (i >= 1) {
                float ds = mv < EPS_ ? EPS_ : mv;
                acc += 0.1f - sqrtf(ds) * __expf(-ds * (1.0f / H2));
            }
        }
    }

    // deterministic block reduction (non-leader lanes contribute 0)
#pragma unroll
    for (int off = 16; off > 0; off >>= 1)
        acc += __shfl_down_sync(0xffffffffu, acc, off);
    const int wid = tid >> 5;
    if (lane == 0) red[wid] = acc;
    __syncthreads();
    if (tid == 0) {
        float s = 0.0f;
#pragma unroll
        for (int w = 0; w < TPB_G / 32; w++) s += red[w];
        g_partials[blockIdx.x] = s;
        __threadfence();
        unsigned tk = atomicAdd(&g_ticket, 1u);
        is_last = (tk == gridDim.x - 1) ? 1 : 0;
    }
    __syncthreads();

    if (is_last && tid < 32) {
        const int nb = gridDim.x;
        float s = 0.0f;
        for (int i = lane; i < nb; i += 32) s += g_partials[i];
#pragma unroll
        for (int off = 16; off > 0; off >>= 1)
            s += __shfl_down_sync(0xffffffffu, s, off);
        if (lane == 0) {
            out[0] = s * inv_count;
            g_ticket = 0;
        }
    }
}

extern "C" void kernel_launch(void* const* d_in, const int* in_sizes, int n_in,
                              void* d_out, int out_size) {
    const float* pred = (const float*)d_in[0];
    const int B = in_sizes[0] / (N_PTS * 3);
    const int nblocks = B * GBLK_PER_BATCH;

    density_cells<<<B * 16, 256>>>(pred);
    density_scan<<<B, 1024>>>();
    density_scatter<<<B * 16, 256>>>();

    const float inv_count = 1.0f / (float)((long long)B * N_PTS * (TOPK - 1));
    density_group<<<nblocks, TPB_G>>>((float*)d_out, inv_count);
}

// round 11
// speedup vs baseline: 1.4690x; 1.4690x over previous
#include <cuda_runtime.h>
#include <cuda_bf16.h>

#define N_PTS   4096
#define NSAMPLE 9
#define TOPK    5
#define R2      0.01f
#define H2      0.0144f
#define EPS_    1e-12f
#define MAXB    8
#define GRID_D  10
#define NCELL   1000
#define IMAX    0x7fffffff

#define LPQ     4                          // lanes per query
#define QPB     32                         // queries per block
#define TPB_G   (QPB * LPQ)                // 128 threads
#define NWARP   (TPB_G / 32)               // 4
#define GBLK_PER_BATCH (N_PTS / QPB)       // 128 blocks per batch
#define CAPL    16                         // buffered hits per lane

// cell-sorted points: xyz + original index in .w
__device__ float4 g_pts[MAXB * N_PTS];
// points by ORIGINAL index: xyz + cell id in .w (epilogue reads xyz only)
__device__ float4 g_org[MAXB * N_PTS];
__device__ int    g_hist[MAXB * NCELL];    // zero at load; re-zeroed by density_scan
__device__ int    g_cur [MAXB * NCELL];
__device__ int    g_cs  [MAXB * (NCELL + 1)];
__device__ float  g_partials[MAXB * GBLK_PER_BATCH];
__device__ unsigned int g_ticket;          // zero-init; reset by last block each launch

// ---------------- Kernel A1: cell ids + histogram (wide) -------------------
__global__ void __launch_bounds__(256)
density_cells(const float* __restrict__ pred) {
    const int b   = blockIdx.x >> 4;              // 16 blocks per batch
    const int sub = blockIdx.x & 15;
    const int i   = sub * 256 + threadIdx.x;      // 0..4095
    const float* pb = pred + (size_t)b * N_PTS * 3;

    float x = pb[i * 3 + 0], y = pb[i * 3 + 1], z = pb[i * 3 + 2];
    int cx = min((int)(x * 10.0f), GRID_D - 1);
    int cy = min((int)(y * 10.0f), GRID_D - 1);
    int cz = min((int)(z * 10.0f), GRID_D - 1);
    int c = cz * 100 + cy * 10 + cx;
    g_org[b * N_PTS + i] = make_float4(x, y, z, __int_as_float(c));
    atomicAdd(&g_hist[b * NCELL + c], 1);
}

// ---------------- Kernel A2: per-batch scan of the histogram ---------------
__global__ void __launch_bounds__(1024)
density_scan() {
    __shared__ int wsum[32];
    const int b    = blockIdx.x;
    const int tid  = threadIdx.x;
    const int lane = tid & 31;
    const int wid  = tid >> 5;

    const int h = (tid < NCELL) ? g_hist[b * NCELL + tid] : 0;
    if (tid < NCELL) g_hist[b * NCELL + tid] = 0;   // re-zero for next launch/replay
    int x = h;
#pragma unroll
    for (int off = 1; off < 32; off <<= 1) {
        int y = __shfl_up_sync(0xffffffffu, x, off);
        if (lane >= off) x += y;
    }
    if (lane == 31) wsum[wid] = x;
    __syncthreads();
    if (wid == 0) {
        int ws = wsum[lane];
        int wx = ws;
#pragma unroll
        for (int off = 1; off < 32; off <<= 1) {
            int y = __shfl_up_sync(0xffffffffu, wx, off);
            if (lane >= off) wx += y;
        }
        wsum[lane] = wx - ws;
    }
    __syncthreads();
    const int incl = x + wsum[wid];              // inclusive over cells [0..tid]

    if (tid == 0) g_cs[b * (NCELL + 1)] = 0;
    if (tid < NCELL) {
        g_cs [b * (NCELL + 1) + tid + 1] = incl;
        g_cur[b * NCELL + tid]           = incl - h;   // exclusive prefix = cstart
    }
}

// ---------------- Kernel A3: scatter into sorted order (wide) --------------
__global__ void __launch_bounds__(256)
density_scatter() {
    const int b   = blockIdx.x >> 4;
    const int sub = blockIdx.x & 15;
    const int i   = sub * 256 + threadIdx.x;

    float4 f = g_org[b * N_PTS + i];
    int c = __float_as_int(f.w);
    int pos = atomicAdd(&g_cur[b * NCELL + c], 1);
    g_pts[b * N_PTS + pos] = make_float4(f.x, f.y, f.z, __int_as_float(i));
}

// ---------------- Kernel B: quad-cooperative, lane-buffered selection ------
__global__ void __launch_bounds__(TPB_G)
density_group(float* __restrict__ out, float inv_count) {
    // per-lane hit segments, bank = lane (conflict-free): [warp][slot][lane]
    __shared__ int   sbuf[NWARP][CAPL][32];
    __shared__ float red[NWARP];
    __shared__ int   is_last;

    const int b     = blockIdx.x / GBLK_PER_BATCH;
    const int blk   = blockIdx.x % GBLK_PER_BATCH;
    const int goff  = b * N_PTS;
    const int csoff = b * (NCELL + 1);

    const int tid    = threadIdx.x;
    const int lane   = tid & 31;
    const int wid    = tid >> 5;
    const int tq     = tid & (LPQ - 1);      // lane within quad
    const int qlocal = tid >> 2;             // query within block
    const int t      = blk * QPB + qlocal;   // query in sorted order

    const float4 q = __ldg(&g_pts[goff + t]);

    const int cy = min((int)(q.y * 10.0f), GRID_D - 1);
    const int cz = min((int)(q.z * 10.0f), GRID_D - 1);
    const int y0 = max(cy - 1, 0), y1 = min(cy + 1, GRID_D - 1);
    const int z0 = max(cz - 1, 0), z1 = min(cz + 1, GRID_D - 1);

    // scan phase: cheap append of in-ball indices into this lane's segment
    int myCnt = 0;
    for (int zz = z0; zz <= z1; zz++) {
        const float dzb = fmaxf(0.0f, fmaxf(zz * 0.1f - q.z, q.z - (zz + 1) * 0.1f));
        const float dz2 = dzb * dzb;
        for (int yy = y0; yy <= y1; yy++) {
            const float dyb = fmaxf(0.0f, fmaxf(yy * 0.1f - q.y, q.y - (yy + 1) * 0.1f));
            const float rem = R2 + 1e-7f - fmaf(dyb, dyb, dz2);
            if (rem < 0.0f) continue;                 // row can't contain in-ball pts
            const float dxm = sqrtf(rem);             // max |px - qx| for this row
            const int xa = max(0, (int)((q.x - dxm) * 10.0f));
            const int xb = min(GRID_D - 1, (int)((q.x + dxm) * 10.0f));

            const int rowbase = zz * 100 + yy * 10;
            const int jb = __ldg(&g_cs[csoff + rowbase + xa]);
            const int je = __ldg(&g_cs[csoff + rowbase + xb + 1]);

            // software-pipelined candidate loop (prefetch next float4)
            int j = jb + tq;
            bool have = j < je;
            float4 pn;
            if (have) pn = __ldg(&g_pts[goff + j]);
            while (have) {
                const float4 p = pn;
                const int jn = j + LPQ;
                have = jn < je;
                if (have) pn = __ldg(&g_pts[goff + jn]);
                j = jn;

                float dx  = q.x - p.x;
                float dy  = q.y - p.y;
                float dzp = q.z - p.z;
                float d2 = fmaf(dx, dx, fmaf(dy, dy, dzp * dzp));
                if (d2 <= R2 && myCnt < CAPL) {
                    sbuf[wid][myCnt][lane] = __float_as_int(p.w);
                    myCnt++;
                }
            }
        }
    }

    // selection phase: 9 smallest indices of this lane's buffered hits
    int idx9[NSAMPLE];
#pragma unroll
    for (int k = 0; k < NSAMPLE; k++) idx9[k] = IMAX;

    for (int e = 0; e < myCnt; e++) {
        int ci = sbuf[wid][e][lane];
        if (ci < idx9[NSAMPLE - 1]) {
#pragma unroll
            for (int k = 0; k < NSAMPLE; k++) {   // branchless IMNMX chain
                int lo = min(idx9[k], ci);
                ci      = max(idx9[k], ci);
                idx9[k] = lo;
            }
        }
    }

    // quad merge (indices only): 9 pop-min rounds over 4 sorted per-lane lists
    int mi9[NSAMPLE];
#pragma unroll
    for (int k = 0; k < NSAMPLE; k++) {
        int bi = idx9[0];
        int oi = __shfl_xor_sync(0xffffffffu, bi, 1);
        bi = min(bi, oi);
        oi = __shfl_xor_sync(0xffffffffu, bi, 2);
        bi = min(bi, oi);
        mi9[k] = bi;
        if (idx9[0] == bi && bi != IMAX) {   // this lane pops its head
#pragma unroll
            for (int s = 0; s < NSAMPLE - 1; s++) idx9[s] = idx9[s + 1];
            idx9[NSAMPLE - 1] = IMAX;
        }
    }

    // epilogue on quad leader: recompute the 9 values (bit-identical fmaf form)
    float acc = 0.0f;
    if (tq == 0) {
        float m9[NSAMPLE];
#pragma unroll
        for (int k = 0; k < NSAMPLE; k++) {
            const int ik = (mi9[k] == IMAX) ? mi9[0] : mi9[k];
            const float4 p = __ldg(&g_org[goff + ik]);
            float dx = q.x - p.x, dy = q.y - p.y, dzp = q.z - p.z;
            m9[k] = fmaf(dx, dx, fmaf(dy, dy, dzp * dzp));
        }

#pragma unroll
        for (int i = 0; i < TOPK; i++) {
            int   mi = i;
            float mv = m9[i];
#pragma unroll
            for (int j = i + 1; j < NSAMPLE; j++)
                if (m9[j] < mv) { mv = m9[j]; mi = j; }
            m9[mi] = m9[i];
            m9[i]  = mv;
            if (i >= 1) {
                float ds = mv < EPS_ ? EPS_ : mv;
                acc += 0.1f - sqrtf(ds) * __expf(-ds * (1.0f / H2));
            }
        }
    }

    // deterministic block reduction (non-leader lanes contribute 0)
#pragma unroll
    for (int off = 16; off > 0; off >>= 1)
        acc += __shfl_down_sync(0xffffffffu, acc, off);
    if (lane == 0) red[wid] = acc;
    __syncthreads();
    if (tid == 0) {
        float s = 0.0f;
#pragma unroll
        for (int w = 0; w < NWARP; w++) s += red[w];
        g_partials[blockIdx.x] = s;
        __threadfence();
        unsigned tk = atomicAdd(&g_ticket, 1u);
        is_last = (tk == gridDim.x - 1) ? 1 : 0;
    }
    __syncthreads();

    if (is_last && tid < 32) {
        const int nb = gridDim.x;
        float s = 0.0f;
        for (int i = lane; i < nb; i += 32) s += g_partials[i];
#pragma unroll
        for (int off = 16; off > 0; off >>= 1)
            s += __shfl_down_sync(0xffffffffu, s, off);
        if (lane == 0) {
            out[0] = s * inv_count;
            g_ticket = 0;
        }
    }
}

extern "C" void kernel_launch(void* const* d_in, const int* in_sizes, int n_in,
                              void* d_out, int out_size) {
    const float* pred = (const float*)d_in[0];
    const int B = in_sizes[0] / (N_PTS * 3);
    const int nblocks = B * GBLK_PER_BATCH;

    density_cells<<<B * 16, 256>>>(pred);
    density_scan<<<B, 1024>>>();
    density_scatter<<<B * 16, 256>>>();

    const float inv_count = 1.0f / (float)((long long)B * N_PTS * (TOPK - 1));
    density_group<<<nblocks, TPB_G>>>((float*)d_out, inv_count);
}

// round 12
// speedup vs baseline: 1.6020x; 1.0906x over previous
#include <cuda_runtime.h>
#include <cuda_bf16.h>

#define N_PTS   4096
#define NSAMPLE 9
#define TOPK    5
#define R2      0.01f
#define H2      0.0144f
#define EPS_    1e-12f
#define MAXB    8
#define GRID_D  10
#define NCELL   1000
#define IMAX    0x7fffffff

#define LPQ     4                          // lanes per query
#define QPB     32                         // queries per block
#define TPB_G   (QPB * LPQ)                // 128 threads
#define NWARP   (TPB_G / 32)               // 4
#define GBLK_PER_BATCH (N_PTS / QPB)       // 128 blocks per batch
#define CAPL    16                         // buffered hits per lane

// cell-sorted points: xyz + original index in .w
__device__ float4 g_pts[MAXB * N_PTS];
// points by ORIGINAL index (epilogue value recompute)
__device__ float4 g_org[MAXB * N_PTS];
__device__ int    g_cs [MAXB * (NCELL + 1)];
__device__ float  g_partials[MAXB * GBLK_PER_BATCH];
__device__ unsigned int g_ticket;          // zero-init; reset by last block each launch

// ---------------- Kernel A: monolithic counting sort (1 block / batch) -----
// dyn smem: stash float4[4096] (64K) | hist int[1024] (4K) | cstart int[1024] (4K) | wsum int[32]
#define BIN_SMEM (65536 + 4096 + 4096 + 128)

__global__ void __launch_bounds__(1024)
density_bin(const float* __restrict__ pred) {
    extern __shared__ char smem[];
    float4* stash  = (float4*)smem;
    int*    hist   = (int*)(smem + 65536);
    int*    cstart = (int*)(smem + 69632);
    int*    wsum   = (int*)(smem + 73728);

    const int b    = blockIdx.x;
    const int tid  = threadIdx.x;
    const int lane = tid & 31;
    const int wid  = tid >> 5;
    const float* pb = pred + (size_t)b * N_PTS * 3;

    if (tid < NCELL) hist[tid] = 0;
    __syncthreads();

    // pass 1: cell + histogram + smem stash + g_org (single gmem read of pred)
#pragma unroll
    for (int it = 0; it < N_PTS / 1024; it++) {
        const int i = it * 1024 + tid;
        float x = pb[i * 3 + 0], y = pb[i * 3 + 1], z = pb[i * 3 + 2];
        int cx = min((int)(x * 10.0f), GRID_D - 1);
        int cy = min((int)(y * 10.0f), GRID_D - 1);
        int cz = min((int)(z * 10.0f), GRID_D - 1);
        int c = cz * 100 + cy * 10 + cx;
        stash[i] = make_float4(x, y, z, __int_as_float(c));
        g_org[b * N_PTS + i] = make_float4(x, y, z, 0.0f);
        atomicAdd(&hist[c], 1);
    }
    __syncthreads();

    // warp-shuffle inclusive scan over 1024 slots (hist padded with 0)
    int x = (tid < NCELL) ? hist[tid] : 0;
#pragma unroll
    for (int off = 1; off < 32; off <<= 1) {
        int y = __shfl_up_sync(0xffffffffu, x, off);
        if (lane >= off) x += y;
    }
    if (lane == 31) wsum[wid] = x;
    __syncthreads();
    if (wid == 0) {
        int ws = wsum[lane];
        int wx = ws;
#pragma unroll
        for (int off = 1; off < 32; off <<= 1) {
            int y = __shfl_up_sync(0xffffffffu, wx, off);
            if (lane >= off) wx += y;
        }
        wsum[lane] = wx - ws;   // exclusive warp offset
    }
    __syncthreads();
    const int incl = x + wsum[wid];   // inclusive over cells [0..tid]

    if (tid == 0) { cstart[0] = 0; g_cs[b * (NCELL + 1)] = 0; }
    if (tid < NCELL) {
        cstart[tid + 1] = incl;
        g_cs[b * (NCELL + 1) + tid + 1] = incl;
        hist[tid] = 0;   // reuse as cursor
    }
    __syncthreads();

    // pass 2: scatter from smem stash
#pragma unroll
    for (int it = 0; it < N_PTS / 1024; it++) {
        const int i = it * 1024 + tid;
        float4 f = stash[i];
        int c = __float_as_int(f.w);
        int pos = cstart[c] + atomicAdd(&hist[c], 1);
        g_pts[b * N_PTS + pos] = make_float4(f.x, f.y, f.z, __int_as_float(i));
    }
}

// ---------------- Kernel B: quad-cooperative, lane-buffered selection ------
__global__ void __launch_bounds__(TPB_G)
density_group(float* __restrict__ out, float inv_count) {
    // per-lane hit segments, bank = lane (conflict-free): [warp][slot][lane]
    __shared__ int   sbuf[NWARP][CAPL][32];
    __shared__ float red[NWARP];
    __shared__ int   is_last;

    const int b     = blockIdx.x / GBLK_PER_BATCH;
    const int blk   = blockIdx.x % GBLK_PER_BATCH;
    const int goff  = b * N_PTS;
    const int csoff = b * (NCELL + 1);

    const int tid    = threadIdx.x;
    const int lane   = tid & 31;
    const int wid    = tid >> 5;
    const int tq     = tid & (LPQ - 1);      // lane within quad
    const int qlocal = tid >> 2;             // query within block
    const int t      = blk * QPB + qlocal;   // query in sorted order

    const float4 q = __ldg(&g_pts[goff + t]);

    const int cy = min((int)(q.y * 10.0f), GRID_D - 1);
    const int cz = min((int)(q.z * 10.0f), GRID_D - 1);
    const int y0 = max(cy - 1, 0), y1 = min(cy + 1, GRID_D - 1);
    const int z0 = max(cz - 1, 0), z1 = min(cz + 1, GRID_D - 1);

    // scan phase: cheap append of in-ball indices into this lane's segment
    int myCnt = 0;
    for (int zz = z0; zz <= z1; zz++) {
        const float dzb = fmaxf(0.0f, fmaxf(zz * 0.1f - q.z, q.z - (zz + 1) * 0.1f));
        const float dz2 = dzb * dzb;
        for (int yy = y0; yy <= y1; yy++) {
            const float dyb = fmaxf(0.0f, fmaxf(yy * 0.1f - q.y, q.y - (yy + 1) * 0.1f));
            const float rem = R2 + 1e-7f - fmaf(dyb, dyb, dz2);
            if (rem < 0.0f) continue;                 // row can't contain in-ball pts
            const float dxm = sqrtf(rem);             // max |px - qx| for this row
            const int xa = max(0, (int)((q.x - dxm) * 10.0f));
            const int xb = min(GRID_D - 1, (int)((q.x + dxm) * 10.0f));

            const int rowbase = zz * 100 + yy * 10;
            const int jb = __ldg(&g_cs[csoff + rowbase + xa]);
            const int je = __ldg(&g_cs[csoff + rowbase + xb + 1]);

            // software-pipelined candidate loop (prefetch next float4)
            int j = jb + tq;
            bool have = j < je;
            float4 pn;
            if (have) pn = __ldg(&g_pts[goff + j]);
            while (have) {
                const float4 p = pn;
                const int jn = j + LPQ;
                have = jn < je;
                if (have) pn = __ldg(&g_pts[goff + jn]);
                j = jn;

                float dx  = q.x - p.x;
                float dy  = q.y - p.y;
                float dzp = q.z - p.z;
                float d2 = fmaf(dx, dx, fmaf(dy, dy, dzp * dzp));
                if (d2 <= R2 && myCnt < CAPL) {
                    sbuf[wid][myCnt][lane] = __float_as_int(p.w);
                    myCnt++;
                }
            }
        }
    }

    // selection phase: 9 smallest indices of this lane's buffered hits
    int idx9[NSAMPLE];
#pragma unroll
    for (int k = 0; k < NSAMPLE; k++) idx9[k] = IMAX;

    for (int e = 0; e < myCnt; e++) {
        int ci = sbuf[wid][e][lane];
        if (ci < idx9[NSAMPLE - 1]) {
#pragma unroll
            for (int k = 0; k < NSAMPLE; k++) {   // branchless IMNMX chain
                int lo = min(idx9[k], ci);
                ci      = max(idx9[k], ci);
                idx9[k] = lo;
            }
        }
    }

    // quad merge (indices only): 9 pop-min rounds over 4 sorted per-lane lists
    int mi9[NSAMPLE];
#pragma unroll
    for (int k = 0; k < NSAMPLE; k++) {
        int bi = idx9[0];
        int oi = __shfl_xor_sync(0xffffffffu, bi, 1);
        bi = min(bi, oi);
        oi = __shfl_xor_sync(0xffffffffu, bi, 2);
        bi = min(bi, oi);
        mi9[k] = bi;
        if (idx9[0] == bi && bi != IMAX) {   // this lane pops its head
#pragma unroll
            for (int s = 0; s < NSAMPLE - 1; s++) idx9[s] = idx9[s + 1];
            idx9[NSAMPLE - 1] = IMAX;
        }
    }

    // epilogue on quad leader: recompute the 9 values (bit-identical fmaf form)
    float acc = 0.0f;
    if (tq == 0) {
        float m9[NSAMPLE];
#pragma unroll
        for (int k = 0; k < NSAMPLE; k++) {
            const int ik = (mi9[k] == IMAX) ? mi9[0] : mi9[k];
            const float4 p = __ldg(&g_org[goff + ik]);
            float dx = q.x - p.x, dy = q.y - p.y, dzp = q.z - p.z;
            m9[k] = fmaf(dx, dx, fmaf(dy, dy, dzp * dzp));
        }

#pragma unroll
        for (int i = 0; i < TOPK; i++) {
            int   mi = i;
            float mv = m9[i];
#pragma unroll
            for (int j = i + 1; j < NSAMPLE; j++)
                if (m9[j] < mv) { mv = m9[j]; mi = j; }
            m9[mi] = m9[i];
            m9[i]  = mv;
            if (i >= 1) {
                float ds = mv < EPS_ ? EPS_ : mv;
                acc += 0.1f - sqrtf(ds) * __expf(-ds * (1.0f / H2));
            }
        }
    }

    // deterministic block reduction (non-leader lanes contribute 0)
#pragma unroll
    for (int off = 16; off > 0; off >>= 1)
        acc += __shfl_down_sync(0xffffffffu, acc, off);
    if (lane == 0) red[wid] = acc;
    __syncthreads();
    if (tid == 0) {
        float s = 0.0f;
#pragma unroll
        for (int w = 0; w < NWARP; w++) s += red[w];
        g_partials[blockIdx.x] = s;
        __threadfence();
        unsigned tk = atomicAdd(&g_ticket, 1u);
        is_last = (tk == gridDim.x - 1) ? 1 : 0;
    }
    __syncthreads();

    if (is_last && tid < 32) {
        const int nb = gridDim.x;
        float s = 0.0f;
        for (int i = lane; i < nb; i += 32) s += g_partials[i];
#pragma unroll
        for (int off = 16; off > 0; off >>= 1)
            s += __shfl_down_sync(0xffffffffu, s, off);
        if (lane == 0) {
            out[0] = s * inv_count;
            g_ticket = 0;
        }
    }
}

extern "C" void kernel_launch(void* const* d_in, const int* in_sizes, int n_in,
                              void* d_out, int out_size) {
    const float* pred = (const float*)d_in[0];
    const int B = in_sizes[0] / (N_PTS * 3);
    const int nblocks = B * GBLK_PER_BATCH;

    cudaFuncSetAttribute(density_bin,
                         cudaFuncAttributeMaxDynamicSharedMemorySize, BIN_SMEM);

    density_bin<<<B, 1024, BIN_SMEM>>>(pred);

    const float inv_count = 1.0f / (float)((long long)B * N_PTS * (TOPK - 1));
    density_group<<<nblocks, TPB_G>>>((float*)d_out, inv_count);
}